// round 8
// baseline (speedup 1.0000x reference)
#include <cuda_runtime.h>
#include <cuda_bf16.h>
#include <cstdint>

#define GV 1024
#define GB 128
#define NN (GB * GV)          // 131072 columns (channel-major)
#define KORD 5
#define CKP 960               // padded K stride for split weights
#define FKCAP (960 * 16384)   // max CK*stripeN elements per plane (~31.5MB bf16)

// ---------------- scratch (device globals; no allocation) ----------------
__device__ __nv_bfloat16 g_fkh[FKCAP];     // Fk hi plane [CK][stripeN] (stripe-local)
__device__ __nv_bfloat16 g_fkl[FKCAP];     // Fk lo plane
__device__ float g_act[(size_t)192 * NN];  // conv output Y [F][NN] fp32
__device__ float g_bn_s[192];
__device__ float g_bn_t[192];
__device__ double g_dsum[192];
__device__ double g_dsq[192];
__device__ __nv_bfloat16 g_wh[192 * CKP];  // W hi plane [F][960]
__device__ __nv_bfloat16 g_wl[192 * CKP];  // W lo plane [F][960]

// ---------------- helpers ----------------
__device__ __forceinline__ uint32_t smem_u32(const void* p) {
    uint32_t a;
    asm("{ .reg .u64 t; cvta.to.shared.u64 t, %1; cvt.u32.u64 %0, t; }" : "=r"(a) : "l"(p));
    return a;
}

__device__ __forceinline__ void mma_bf16(float* d, const uint32_t* a, const uint32_t* b) {
    asm volatile(
        "mma.sync.aligned.m16n8k16.row.col.f32.bf16.bf16.f32 "
        "{%0,%1,%2,%3}, {%4,%5,%6,%7}, {%8,%9}, {%0,%1,%2,%3};"
        : "+f"(d[0]), "+f"(d[1]), "+f"(d[2]), "+f"(d[3])
        : "r"(a[0]), "r"(a[1]), "r"(a[2]), "r"(a[3]), "r"(b[0]), "r"(b[1]));
}

#define LDSM_X4(r0, r1, r2, r3, addr) \
    asm volatile("ldmatrix.sync.aligned.m8n8.x4.shared.b16 {%0,%1,%2,%3}, [%4];" \
                 : "=r"(r0), "=r"(r1), "=r"(r2), "=r"(r3) : "r"(addr))
#define LDSM_X4T(r0, r1, r2, r3, addr) \
    asm volatile("ldmatrix.sync.aligned.m8n8.x4.trans.shared.b16 {%0,%1,%2,%3}, [%4];" \
                 : "=r"(r0), "=r"(r1), "=r"(r2), "=r"(r3) : "r"(addr))

#define CP_ASYNC16(dst, src) \
    asm volatile("cp.async.ca.shared.global [%0], [%1], 16;" :: "r"(dst), "l"(src) : "memory")
#define CP_COMMIT() asm volatile("cp.async.commit_group;" ::: "memory")
#define CP_WAIT0()  asm volatile("cp.async.wait_group 0;" ::: "memory")

// ---------------- W split + accumulator zeroing ----------------
__global__ void wsplit(const float* __restrict__ W, int F, int CK) {
    int idx = blockIdx.x * 256 + threadIdx.x;
    if (blockIdx.x == 0 && threadIdx.x < 192) {
        g_dsum[threadIdx.x] = 0.0;
        g_dsq[threadIdx.x]  = 0.0;
    }
    if (idx >= F * CKP) return;
    int k = idx % CKP;
    int f = idx / CKP;
    float v = (k < CK) ? W[(size_t)f * CK + k] : 0.f;
    __nv_bfloat16 h = __float2bfloat16_rn(v);
    g_wh[idx] = h;
    g_wl[idx] = __float2bfloat16_rn(v - __bfloat162float(h));
}

// ---------------- Chebyshev expansion (stripe-local fk output) ----------------
__device__ __forceinline__ float rsd_of(int i, int j) {
    int deg = (i > 0) + (i < 31) + (j > 0) + (j < 31);
    return (deg == 4) ? 0.5f : (deg == 3 ? 0.57735026918962576f : 0.70710678118654752f);
}

__device__ __forceinline__ void store_split(size_t idx, float x) {
    __nv_bfloat16 h = __float2bfloat16_rn(x);
    g_fkh[idx] = h;
    g_fkl[idx] = __float2bfloat16_rn(x - __bfloat162float(h));
}

__global__ void cheb_expand(const float* __restrict__ xin, int C, int layer0,
                            int b0, int stripeN) {
    __shared__ float s[GV];
    const int v = threadIdx.x;
    const int c = blockIdx.x;
    const int bl = blockIdx.y;           // batch within stripe
    const int b = b0 + bl;               // global batch
    const int i = v >> 5, j = v & 31;

    float x;
    if (layer0) {
        x = xin[((size_t)b * C + c) * GV + v];
    } else {
        x = g_act[(size_t)c * NN + (size_t)b * GV + v];
        x = fmaxf(fmaf(x, g_bn_s[c], g_bn_t[c]), 0.0f);
    }

    const float rv = rsd_of(i, j);
    const float w_up = (i > 0)  ? rv * rsd_of(i - 1, j) : 0.f;
    const float w_dn = (i < 31) ? rv * rsd_of(i + 1, j) : 0.f;
    const float w_lf = (j > 0)  ? rv * rsd_of(i, j - 1) : 0.f;
    const float w_rt = (j < 31) ? rv * rsd_of(i, j + 1) : 0.f;
    const int up = (i > 0)  ? v - 32 : v;
    const int dn = (i < 31) ? v + 32 : v;
    const int lf = (j > 0)  ? v - 1  : v;
    const int rt = (j < 31) ? v + 1  : v;

    const size_t base = (size_t)(c * KORD) * stripeN + (size_t)bl * GV + v;

    store_split(base, x);
    s[v] = x;
    __syncthreads();
    float t1 = -(w_up * s[up] + w_dn * s[dn] + w_lf * s[lf] + w_rt * s[rt]);
    store_split(base + stripeN, t1);

    float tp = x, tc = t1;
#pragma unroll
    for (int k = 2; k < KORD; k++) {
        __syncthreads();
        s[v] = tc;
        __syncthreads();
        float l = -(w_up * s[up] + w_dn * s[dn] + w_lf * s[lf] + w_rt * s[rt]);
        float tn = fmaf(2.0f, l, -tp);
        store_split(base + (size_t)k * stripeN, tn);
        tp = tc;
        tc = tn;
    }
}

// ---------------- tensor-core GEMM (mma.sync bf16 hi/lo 3-term) + fused BN stats ----
// CTA: 96m x 128n, BK=32. 8 warps = 2(m) x 4(n); warp tile 48m x 32n.
// smem/stage: Ah[96][80B] Al[96][80B] Bh[32][272B] Bl[32][272B] = 32768 B
#define ROWA 80
#define ROWBB 272
#define SZ_AP (96 * ROWA)                 // 7680
#define SZ_BP (32 * ROWBB)                // 8704
#define OFF_AH 0
#define OFF_AL SZ_AP
#define OFF_BH (2 * SZ_AP)
#define OFF_BL (2 * SZ_AP + SZ_BP)
#define STAGE  (2 * SZ_AP + 2 * SZ_BP)    // 32768
#define SMEM_GEMM (2 * STAGE)             // 65536

__global__ void __launch_bounds__(256, 2)
gemm_mma(int F, int CK, int nbase, int stripeN) {
    extern __shared__ char smem[];
    const uint32_t sbase = smem_u32(smem);

    const int tid  = threadIdx.x;
    const int lane = tid & 31;
    const int wid  = tid >> 5;
    const int wm   = wid & 1;        // 0..1  (m)
    const int wn   = wid >> 1;       // 0..3  (n)
    const int g    = lane >> 2;      // 0..7
    const int t4   = lane & 3;       // 0..3
    const int l15  = lane & 15;
    const int lhi  = lane >> 4;      // 0..1

    const int m0 = blockIdx.x * 96;
    const int n0 = blockIdx.y * 128;           // stripe-local
    const int ns = (CK + 31) >> 5;

    float acc[3][4][4];
#pragma unroll
    for (int a = 0; a < 3; a++)
#pragma unroll
        for (int b = 0; b < 4; b++)
#pragma unroll
            for (int c = 0; c < 4; c++) acc[a][b][c] = 0.f;

    // ---- async load of one stage (A: 768 chunks, B: 1024 chunks) ----
    auto load_stage = [&](uint32_t sdst, int k0) {
#pragma unroll
        for (int i = 0; i < 3; i++) {              // A planes
            int e = tid + 256 * i;
            int p = e >= 384;
            int id = e - 384 * p;
            int r = id >> 2, q = id & 3;
            const __nv_bfloat16* src = (p ? g_wl : g_wh) + (size_t)(m0 + r) * CKP + k0 + q * 8;
            CP_ASYNC16(sdst + (p ? OFF_AL : OFF_AH) + r * ROWA + q * 16, src);
        }
#pragma unroll
        for (int i = 0; i < 4; i++) {              // B planes
            int e = tid + 256 * i;
            int p = e >= 512;
            int id = e - 512 * p;
            int k = id >> 4, cc = id & 15;
            const __nv_bfloat16* src = (p ? g_fkl : g_fkh)
                + (size_t)(k0 + k) * stripeN + n0 + cc * 8;
            CP_ASYNC16(sdst + (p ? OFF_BL : OFF_BH) + k * ROWBB + cc * 16, src);
        }
        CP_COMMIT();
    };

    load_stage(sbase, 0);
    CP_WAIT0();
    __syncthreads();

    for (int s = 0; s < ns; s++) {
        const uint32_t buf = sbase + (uint32_t)(s & 1) * STAGE;
        const bool more = (s + 1 < ns);
        if (more) load_stage(sbase + (uint32_t)((s + 1) & 1) * STAGE, (s + 1) * 32);

#pragma unroll
        for (int c = 0; c < 2; c++) {
            uint32_t ah[3][4], al[3][4];
#pragma unroll
            for (int mf = 0; mf < 3; mf++) {
                int row = wm * 48 + mf * 16 + l15;
                uint32_t qa = (uint32_t)(2 * c + lhi);
                uint32_t addr = buf + OFF_AH + row * ROWA + qa * 16;
                LDSM_X4(ah[mf][0], ah[mf][1], ah[mf][2], ah[mf][3], addr);
                LDSM_X4(al[mf][0], al[mf][1], al[mf][2], al[mf][3], addr + (OFF_AL - OFF_AH));
            }
            uint32_t bh[2][4], bl[2][4];
#pragma unroll
            for (int p = 0; p < 2; p++) {
                int krow = 16 * c + l15;
                int nbyte = wn * 64 + p * 32 + lhi * 16;
                uint32_t addr = buf + OFF_BH + krow * ROWBB + nbyte;
                LDSM_X4T(bh[p][0], bh[p][1], bh[p][2], bh[p][3], addr);
                LDSM_X4T(bl[p][0], bl[p][1], bl[p][2], bl[p][3], addr + (OFF_BL - OFF_BH));
            }
#pragma unroll
            for (int p = 0; p < 2; p++)
#pragma unroll
                for (int h = 0; h < 2; h++) {
                    int nf = 2 * p + h;
#pragma unroll
                    for (int mf = 0; mf < 3; mf++) {
                        mma_bf16(acc[mf][nf], ah[mf], &bh[p][2 * h]);
                        mma_bf16(acc[mf][nf], al[mf], &bh[p][2 * h]);
                        mma_bf16(acc[mf][nf], ah[mf], &bl[p][2 * h]);
                    }
                }
        }
        if (more) CP_WAIT0();
        __syncthreads();
    }

    // ---- epilogue 1: fragments -> g_act (global columns) ----
    const int gcol0 = nbase + n0;
#pragma unroll
    for (int mf = 0; mf < 3; mf++) {
        int mrow = m0 + wm * 48 + mf * 16 + g;
#pragma unroll
        for (int nf = 0; nf < 4; nf++) {
            int col = gcol0 + wn * 32 + nf * 8 + 2 * t4;
            *(float2*)(g_act + (size_t)mrow * NN + col) =
                make_float2(acc[mf][nf][0], acc[mf][nf][1]);
            *(float2*)(g_act + (size_t)(mrow + 8) * NN + col) =
                make_float2(acc[mf][nf][2], acc[mf][nf][3]);
        }
    }

    // ---- epilogue 2: fused BN partial stats ----
    float* reds = (float*)smem;          // [96][4]
    float* redq = (float*)smem + 384;    // [96][4]
#pragma unroll
    for (int mf = 0; mf < 3; mf++) {
#pragma unroll
        for (int half = 0; half < 2; half++) {
            float s = 0.f, q = 0.f;
#pragma unroll
            for (int nf = 0; nf < 4; nf++) {
                float v0 = acc[mf][nf][2 * half];
                float v1 = acc[mf][nf][2 * half + 1];
                s += v0 + v1;
                q += v0 * v0 + v1 * v1;
            }
            s += __shfl_xor_sync(0xffffffffu, s, 1);
            s += __shfl_xor_sync(0xffffffffu, s, 2);
            q += __shfl_xor_sync(0xffffffffu, q, 1);
            q += __shfl_xor_sync(0xffffffffu, q, 2);
            if (t4 == 0) {
                int row = wm * 48 + mf * 16 + half * 8 + g;
                reds[row * 4 + wn] = s;
                redq[row * 4 + wn] = q;
            }
        }
    }
    __syncthreads();
    if (tid < 96) {
        float s = reds[tid * 4] + reds[tid * 4 + 1] + reds[tid * 4 + 2] + reds[tid * 4 + 3];
        float q = redq[tid * 4] + redq[tid * 4 + 1] + redq[tid * 4 + 2] + redq[tid * 4 + 3];
        atomicAdd(&g_dsum[m0 + tid], (double)s);
        atomicAdd(&g_dsq[m0 + tid],  (double)q);
    }
}

// ---------------- BN finalize ----------------
__global__ void bn_final(const float* __restrict__ gamma, const float* __restrict__ beta, int F) {
    int f = threadIdx.x;
    if (f >= F) return;
    double mean = g_dsum[f] / (double)NN;
    double var  = g_dsq[f] / (double)NN - mean * mean;
    float sc = gamma[f] * rsqrtf((float)var + 1e-5f);
    g_bn_s[f] = sc;
    g_bn_t[f] = beta[f] - (float)mean * sc;
}

// ---------------- classifier ----------------
__global__ void classifier(const float* __restrict__ cw, const float* __restrict__ cb,
                           float* __restrict__ out) {
    const int b0   = blockIdx.x * 4;
    const int lane = threadIdx.x & 31;
    const int warp = threadIdx.x >> 5;

    float acc[4][10];
#pragma unroll
    for (int bb = 0; bb < 4; bb++)
#pragma unroll
        for (int o = 0; o < 10; o++) acc[bb][o] = 0.f;

    const int NF = 96 * GV;
    for (int f = threadIdx.x; f < NF; f += 256) {
        int c = f >> 10, v = f & (GV - 1);
        float sc = g_bn_s[c], sh = g_bn_t[c];
        float w[10];
#pragma unroll
        for (int o = 0; o < 10; o++) w[o] = cw[(size_t)o * NF + f];
#pragma unroll
        for (int bb = 0; bb < 4; bb++) {
            float y = g_act[(size_t)c * NN + (size_t)(b0 + bb) * GV + v];
            float h = fmaxf(fmaf(y, sc, sh), 0.f);
#pragma unroll
            for (int o = 0; o < 10; o++) acc[bb][o] = fmaf(h, w[o], acc[bb][o]);
        }
    }

    __shared__ float part[8][40];
#pragma unroll
    for (int bb = 0; bb < 4; bb++)
#pragma unroll
        for (int o = 0; o < 10; o++) {
            float vsum = acc[bb][o];
#pragma unroll
            for (int off = 16; off > 0; off >>= 1)
                vsum += __shfl_down_sync(0xffffffffu, vsum, off);
            if (lane == 0) part[warp][bb * 10 + o] = vsum;
        }
    __syncthreads();
    if (threadIdx.x < 40) {
        float ssum = 0.f;
#pragma unroll
        for (int wq = 0; wq < 8; wq++) ssum += part[wq][threadIdx.x];
        int bb = threadIdx.x / 10, o = threadIdx.x % 10;
        out[(b0 + bb) * 10 + o] = ssum + cb[o];
    }
}

// ---------------- launch ----------------
extern "C" void kernel_launch(void* const* d_in, const int* in_sizes, int n_in,
                              void* d_out, int out_size) {
    (void)out_size;
    const float* x = (const float*)d_in[0];
    const float* w[7];
    const float* gg[7];
    const float* bb[7];

    if (n_in >= 25 && in_sizes[3] == 96) {  // dict order (w,g,b per layer)
        for (int i = 0; i < 7; i++) {
            w[i]  = (const float*)d_in[2 + 3 * i];
            gg[i] = (const float*)d_in[3 + 3 * i];
            bb[i] = (const float*)d_in[4 + 3 * i];
        }
    } else {                                // signature order
        for (int i = 0; i < 7; i++) {
            w[i]  = (const float*)d_in[2 + i];
            gg[i] = (const float*)d_in[9 + i];
            bb[i] = (const float*)d_in[16 + i];
        }
    }
    const float* clf_w = (const float*)d_in[23];
    const float* clf_b = (const float*)d_in[24];

    static int smem_set = 0;
    if (!smem_set) {
        cudaFuncSetAttribute(gemm_mma, cudaFuncAttributeMaxDynamicSharedMemorySize, SMEM_GEMM);
        smem_set = 1;
    }

    const int CIN[7]  = {3, 96, 96, 96, 192, 192, 192};
    const int FOUT[7] = {96, 96, 96, 192, 192, 192, 96};
    // stripe sizes chosen so CK*stripeN*2planes*2B ~ 63MB (L2-resident fk)
    const int STRN[7] = {131072, 32768, 32768, 32768, 16384, 16384, 16384};

    for (int l = 0; l < 7; l++) {
        const int C = CIN[l], F = FOUT[l], CK = C * KORD;
        const int strN = STRN[l];
        const int nstr = NN / strN;

        wsplit<<<(F * CKP + 255) / 256, 256>>>(w[l], F, CK);

        for (int s = 0; s < nstr; s++) {
            const int nbase = s * strN;
            cheb_expand<<<dim3(C, strN / GV), GV>>>(x, C, l == 0 ? 1 : 0, nbase / GV, strN);
            dim3 grid(F / 96, strN / 128);
            gemm_mma<<<grid, 256, SMEM_GEMM>>>(F, CK, nbase, strN);
        }

        bn_final<<<1, 192>>>(gg[l], bb[l], F);
    }

    classifier<<<32, 256>>>(clf_w, clf_b, (float*)d_out);
}

// round 9
// speedup vs baseline: 1.0659x; 1.0659x over previous
#include <cuda_runtime.h>
#include <cuda_bf16.h>
#include <cstdint>

#define GV 1024
#define GB 128
#define NN (GB * GV)          // 131072 columns (channel-major)
#define KORD 5
#define CKP 960               // padded K stride for split weights

// ---------------- scratch (device globals; no allocation) ----------------
__device__ __nv_bfloat16 g_fkh[(size_t)960 * NN];  // Fk hi plane [CK][NN]
__device__ __nv_bfloat16 g_fkl[(size_t)960 * NN];  // Fk lo plane [CK][NN]
__device__ float g_act[(size_t)192 * NN];          // conv output Y [F][NN] fp32
__device__ float g_bn_s[192];
__device__ float g_bn_t[192];
__device__ double g_dsum[192];
__device__ double g_dsq[192];
__device__ __nv_bfloat16 g_wh[192 * CKP];          // W hi plane [F][960]
__device__ __nv_bfloat16 g_wl[192 * CKP];          // W lo plane [F][960]

// ---------------- helpers ----------------
__device__ __forceinline__ uint32_t smem_u32(const void* p) {
    uint32_t a;
    asm("{ .reg .u64 t; cvta.to.shared.u64 t, %1; cvt.u32.u64 %0, t; }" : "=r"(a) : "l"(p));
    return a;
}

__device__ __forceinline__ void mma_bf16(float* d, const uint32_t* a, const uint32_t* b) {
    asm volatile(
        "mma.sync.aligned.m16n8k16.row.col.f32.bf16.bf16.f32 "
        "{%0,%1,%2,%3}, {%4,%5,%6,%7}, {%8,%9}, {%0,%1,%2,%3};"
        : "+f"(d[0]), "+f"(d[1]), "+f"(d[2]), "+f"(d[3])
        : "r"(a[0]), "r"(a[1]), "r"(a[2]), "r"(a[3]), "r"(b[0]), "r"(b[1]));
}

#define LDSM_X4(r0, r1, r2, r3, addr) \
    asm volatile("ldmatrix.sync.aligned.m8n8.x4.shared.b16 {%0,%1,%2,%3}, [%4];" \
                 : "=r"(r0), "=r"(r1), "=r"(r2), "=r"(r3) : "r"(addr))
#define LDSM_X4T(r0, r1, r2, r3, addr) \
    asm volatile("ldmatrix.sync.aligned.m8n8.x4.trans.shared.b16 {%0,%1,%2,%3}, [%4];" \
                 : "=r"(r0), "=r"(r1), "=r"(r2), "=r"(r3) : "r"(addr))

#define CP_ASYNC16(dst, src) \
    asm volatile("cp.async.ca.shared.global [%0], [%1], 16;" :: "r"(dst), "l"(src) : "memory")
#define CP_COMMIT() asm volatile("cp.async.commit_group;" ::: "memory")
#define CP_WAIT0()  asm volatile("cp.async.wait_group 0;" ::: "memory")

// ---------------- W split + BN finalize (prev layer) + accumulator zeroing ----------------
__global__ void wsplit_bn(const float* __restrict__ W, int F, int CK,
                          const float* __restrict__ gamma_p, const float* __restrict__ beta_p,
                          int Fprev, int do_bn) {
    int idx = blockIdx.x * 256 + threadIdx.x;
    if (blockIdx.x == 0 && threadIdx.x < 192) {
        int f = threadIdx.x;
        if (do_bn && f < Fprev) {
            double mean = g_dsum[f] / (double)NN;
            double var  = g_dsq[f] / (double)NN - mean * mean;
            float sc = gamma_p[f] * rsqrtf((float)var + 1e-5f);
            g_bn_s[f] = sc;
            g_bn_t[f] = beta_p[f] - (float)mean * sc;
        }
        g_dsum[f] = 0.0;
        g_dsq[f]  = 0.0;
    }
    if (idx >= F * CKP) return;
    int k = idx % CKP;
    int f = idx / CKP;
    float v = (k < CK) ? W[(size_t)f * CK + k] : 0.f;
    __nv_bfloat16 h = __float2bfloat16_rn(v);
    g_wh[idx] = h;
    g_wl[idx] = __float2bfloat16_rn(v - __bfloat162float(h));
}

// ---------------- Chebyshev expansion, packed-pair bf16 hi/lo stores ----------------
__device__ __forceinline__ float rsd_of(int i, int j) {
    int deg = (i > 0) + (i < 31) + (j > 0) + (j < 31);
    return (deg == 4) ? 0.5f : (deg == 3 ? 0.57735026918962576f : 0.70710678118654752f);
}

// even-v thread stores the (v, v+1) pair as one 4B word per plane
__device__ __forceinline__ void store_split2(size_t idx, float xe, float xo) {
    __nv_bfloat16 he = __float2bfloat16_rn(xe), ho = __float2bfloat16_rn(xo);
    float re = xe - __bfloat162float(he), ro = xo - __bfloat162float(ho);
    __nv_bfloat16 le = __float2bfloat16_rn(re), lo = __float2bfloat16_rn(ro);
    uint32_t wh = (uint32_t)__bfloat16_as_ushort(he) | ((uint32_t)__bfloat16_as_ushort(ho) << 16);
    uint32_t wl = (uint32_t)__bfloat16_as_ushort(le) | ((uint32_t)__bfloat16_as_ushort(lo) << 16);
    *(uint32_t*)&g_fkh[idx] = wh;
    *(uint32_t*)&g_fkl[idx] = wl;
}

__global__ void cheb_expand(const float* __restrict__ xin, int C, int layer0) {
    __shared__ float s[GV];
    const int v = threadIdx.x;
    const int c = blockIdx.x;
    const int b = blockIdx.y;
    const int i = v >> 5, j = v & 31;

    float x;
    if (layer0) {
        x = xin[((size_t)b * C + c) * GV + v];
    } else {
        x = g_act[(size_t)c * NN + (size_t)b * GV + v];
        x = fmaxf(fmaf(x, g_bn_s[c], g_bn_t[c]), 0.0f);
    }

    const float rv = rsd_of(i, j);
    const float w_up = (i > 0)  ? rv * rsd_of(i - 1, j) : 0.f;
    const float w_dn = (i < 31) ? rv * rsd_of(i + 1, j) : 0.f;
    const float w_lf = (j > 0)  ? rv * rsd_of(i, j - 1) : 0.f;
    const float w_rt = (j < 31) ? rv * rsd_of(i, j + 1) : 0.f;
    const int up = (i > 0)  ? v - 32 : v;
    const int dn = (i < 31) ? v + 32 : v;
    const int lf = (j > 0)  ? v - 1  : v;
    const int rt = (j < 31) ? v + 1  : v;

    const size_t base = (size_t)(c * KORD) * NN + (size_t)b * GV + v;
    const bool even = !(v & 1);

    {
        float xn = __shfl_down_sync(0xffffffffu, x, 1);
        if (even) store_split2(base, x, xn);
    }
    s[v] = x;
    __syncthreads();
    float t1 = -(w_up * s[up] + w_dn * s[dn] + w_lf * s[lf] + w_rt * s[rt]);
    {
        float tn = __shfl_down_sync(0xffffffffu, t1, 1);
        if (even) store_split2(base + NN, t1, tn);
    }

    float tp = x, tc = t1;
#pragma unroll
    for (int k = 2; k < KORD; k++) {
        __syncthreads();
        s[v] = tc;
        __syncthreads();
        float l = -(w_up * s[up] + w_dn * s[dn] + w_lf * s[lf] + w_rt * s[rt]);
        float tn = fmaf(2.0f, l, -tp);
        {
            float tnn = __shfl_down_sync(0xffffffffu, tn, 1);
            if (even) store_split2(base + (size_t)k * NN, tn, tnn);
        }
        tp = tc;
        tc = tn;
    }
}

// ---------------- tensor-core GEMM (mma.sync bf16 hi/lo 3-term) + fused BN stats ----
// CTA: 96m x 128n, BK=32. 8 warps = 2(m) x 4(n); warp tile 48m x 32n.
// smem/stage: Ah[96][80B] Al[96][80B] Bh[32][272B] Bl[32][272B] = 32768 B
#define ROWA 80
#define ROWBB 272
#define SZ_AP (96 * ROWA)                 // 7680
#define SZ_BP (32 * ROWBB)                // 8704
#define OFF_AH 0
#define OFF_AL SZ_AP
#define OFF_BH (2 * SZ_AP)
#define OFF_BL (2 * SZ_AP + SZ_BP)
#define STAGE  (2 * SZ_AP + 2 * SZ_BP)    // 32768
#define SMEM_GEMM (2 * STAGE)             // 65536

__global__ void __launch_bounds__(256, 2)
gemm_mma(int F, int CK) {
    extern __shared__ char smem[];
    const uint32_t sbase = smem_u32(smem);

    const int tid  = threadIdx.x;
    const int lane = tid & 31;
    const int wid  = tid >> 5;
    const int wm   = wid & 1;        // 0..1  (m)
    const int wn   = wid >> 1;       // 0..3  (n)
    const int g    = lane >> 2;      // 0..7
    const int t4   = lane & 3;       // 0..3
    const int l15  = lane & 15;
    const int lhi  = lane >> 4;      // 0..1

    const int m0 = blockIdx.x * 96;
    const int n0 = blockIdx.y * 128;
    const int ns = (CK + 31) >> 5;

    float acc[3][4][4];
#pragma unroll
    for (int a = 0; a < 3; a++)
#pragma unroll
        for (int b = 0; b < 4; b++)
#pragma unroll
            for (int c = 0; c < 4; c++) acc[a][b][c] = 0.f;

    // ---- async load of one stage (A: 768 chunks, B: 1024 chunks) ----
    auto load_stage = [&](uint32_t sdst, int k0) {
#pragma unroll
        for (int i = 0; i < 3; i++) {              // A planes
            int e = tid + 256 * i;
            int p = e >= 384;
            int id = e - 384 * p;
            int r = id >> 2, q = id & 3;
            const __nv_bfloat16* src = (p ? g_wl : g_wh) + (size_t)(m0 + r) * CKP + k0 + q * 8;
            CP_ASYNC16(sdst + (p ? OFF_AL : OFF_AH) + r * ROWA + q * 16, src);
        }
#pragma unroll
        for (int i = 0; i < 4; i++) {              // B planes
            int e = tid + 256 * i;
            int p = e >= 512;
            int id = e - 512 * p;
            int k = id >> 4, cc = id & 15;
            const __nv_bfloat16* src = (p ? g_fkl : g_fkh) + (size_t)(k0 + k) * NN + n0 + cc * 8;
            CP_ASYNC16(sdst + (p ? OFF_BL : OFF_BH) + k * ROWBB + cc * 16, src);
        }
        CP_COMMIT();
    };

    load_stage(sbase, 0);
    CP_WAIT0();
    __syncthreads();

    for (int s = 0; s < ns; s++) {
        const uint32_t buf = sbase + (uint32_t)(s & 1) * STAGE;
        const bool more = (s + 1 < ns);
        if (more) load_stage(sbase + (uint32_t)((s + 1) & 1) * STAGE, (s + 1) * 32);

#pragma unroll
        for (int c = 0; c < 2; c++) {
            uint32_t ah[3][4], al[3][4];
#pragma unroll
            for (int mf = 0; mf < 3; mf++) {
                int row = wm * 48 + mf * 16 + l15;
                uint32_t qa = (uint32_t)(2 * c + lhi);
                uint32_t addr = buf + OFF_AH + row * ROWA + qa * 16;
                LDSM_X4(ah[mf][0], ah[mf][1], ah[mf][2], ah[mf][3], addr);
                LDSM_X4(al[mf][0], al[mf][1], al[mf][2], al[mf][3], addr + (OFF_AL - OFF_AH));
            }
            uint32_t bh[2][4], bl[2][4];
#pragma unroll
            for (int p = 0; p < 2; p++) {
                int krow = 16 * c + l15;
                int nbyte = wn * 64 + p * 32 + lhi * 16;
                uint32_t addr = buf + OFF_BH + krow * ROWBB + nbyte;
                LDSM_X4T(bh[p][0], bh[p][1], bh[p][2], bh[p][3], addr);
                LDSM_X4T(bl[p][0], bl[p][1], bl[p][2], bl[p][3], addr + (OFF_BL - OFF_BH));
            }
#pragma unroll
            for (int p = 0; p < 2; p++)
#pragma unroll
                for (int h = 0; h < 2; h++) {
                    int nf = 2 * p + h;
#pragma unroll
                    for (int mf = 0; mf < 3; mf++) {
                        mma_bf16(acc[mf][nf], ah[mf], &bh[p][2 * h]);
                        mma_bf16(acc[mf][nf], al[mf], &bh[p][2 * h]);
                        mma_bf16(acc[mf][nf], ah[mf], &bl[p][2 * h]);
                    }
                }
        }
        if (more) CP_WAIT0();
        __syncthreads();
    }

    // ---- epilogue 1: fragments -> g_act ----
#pragma unroll
    for (int mf = 0; mf < 3; mf++) {
        int mrow = m0 + wm * 48 + mf * 16 + g;
#pragma unroll
        for (int nf = 0; nf < 4; nf++) {
            int col = n0 + wn * 32 + nf * 8 + 2 * t4;
            *(float2*)(g_act + (size_t)mrow * NN + col) =
                make_float2(acc[mf][nf][0], acc[mf][nf][1]);
            *(float2*)(g_act + (size_t)(mrow + 8) * NN + col) =
                make_float2(acc[mf][nf][2], acc[mf][nf][3]);
        }
    }

    // ---- epilogue 2: fused BN partial stats ----
    float* reds = (float*)smem;          // [96][4]
    float* redq = (float*)smem + 384;    // [96][4]
#pragma unroll
    for (int mf = 0; mf < 3; mf++) {
#pragma unroll
        for (int half = 0; half < 2; half++) {
            float s = 0.f, q = 0.f;
#pragma unroll
            for (int nf = 0; nf < 4; nf++) {
                float v0 = acc[mf][nf][2 * half];
                float v1 = acc[mf][nf][2 * half + 1];
                s += v0 + v1;
                q += v0 * v0 + v1 * v1;
            }
            s += __shfl_xor_sync(0xffffffffu, s, 1);
            s += __shfl_xor_sync(0xffffffffu, s, 2);
            q += __shfl_xor_sync(0xffffffffu, q, 1);
            q += __shfl_xor_sync(0xffffffffu, q, 2);
            if (t4 == 0) {
                int row = wm * 48 + mf * 16 + half * 8 + g;
                reds[row * 4 + wn] = s;
                redq[row * 4 + wn] = q;
            }
        }
    }
    __syncthreads();
    if (tid < 96) {
        float s = reds[tid * 4] + reds[tid * 4 + 1] + reds[tid * 4 + 2] + reds[tid * 4 + 3];
        float q = redq[tid * 4] + redq[tid * 4 + 1] + redq[tid * 4 + 2] + redq[tid * 4 + 3];
        atomicAdd(&g_dsum[m0 + tid], (double)s);
        atomicAdd(&g_dsq[m0 + tid],  (double)q);
    }
}

// ---------------- BN finalize (last layer only) ----------------
__global__ void bn_final(const float* __restrict__ gamma, const float* __restrict__ beta, int F) {
    int f = threadIdx.x;
    if (f >= F) return;
    double mean = g_dsum[f] / (double)NN;
    double var  = g_dsq[f] / (double)NN - mean * mean;
    float sc = gamma[f] * rsqrtf((float)var + 1e-5f);
    g_bn_s[f] = sc;
    g_bn_t[f] = beta[f] - (float)mean * sc;
}

// ---------------- classifier ----------------
__global__ void classifier(const float* __restrict__ cw, const float* __restrict__ cb,
                           float* __restrict__ out) {
    const int b0   = blockIdx.x * 4;
    const int lane = threadIdx.x & 31;
    const int warp = threadIdx.x >> 5;

    float acc[4][10];
#pragma unroll
    for (int bb = 0; bb < 4; bb++)
#pragma unroll
        for (int o = 0; o < 10; o++) acc[bb][o] = 0.f;

    const int NF = 96 * GV;
    for (int f = threadIdx.x; f < NF; f += 256) {
        int c = f >> 10, v = f & (GV - 1);
        float sc = g_bn_s[c], sh = g_bn_t[c];
        float w[10];
#pragma unroll
        for (int o = 0; o < 10; o++) w[o] = cw[(size_t)o * NF + f];
#pragma unroll
        for (int bb = 0; bb < 4; bb++) {
            float y = g_act[(size_t)c * NN + (size_t)(b0 + bb) * GV + v];
            float h = fmaxf(fmaf(y, sc, sh), 0.f);
#pragma unroll
            for (int o = 0; o < 10; o++) acc[bb][o] = fmaf(h, w[o], acc[bb][o]);
        }
    }

    __shared__ float part[8][40];
#pragma unroll
    for (int bb = 0; bb < 4; bb++)
#pragma unroll
        for (int o = 0; o < 10; o++) {
            float vsum = acc[bb][o];
#pragma unroll
            for (int off = 16; off > 0; off >>= 1)
                vsum += __shfl_down_sync(0xffffffffu, vsum, off);
            if (lane == 0) part[warp][bb * 10 + o] = vsum;
        }
    __syncthreads();
    if (threadIdx.x < 40) {
        float ssum = 0.f;
#pragma unroll
        for (int wq = 0; wq < 8; wq++) ssum += part[wq][threadIdx.x];
        int bb = threadIdx.x / 10, o = threadIdx.x % 10;
        out[(b0 + bb) * 10 + o] = ssum + cb[o];
    }
}

// ---------------- launch ----------------
extern "C" void kernel_launch(void* const* d_in, const int* in_sizes, int n_in,
                              void* d_out, int out_size) {
    (void)out_size;
    const float* x = (const float*)d_in[0];
    const float* w[7];
    const float* gg[7];
    const float* bb[7];

    if (n_in >= 25 && in_sizes[3] == 96) {  // dict order (w,g,b per layer)
        for (int i = 0; i < 7; i++) {
            w[i]  = (const float*)d_in[2 + 3 * i];
            gg[i] = (const float*)d_in[3 + 3 * i];
            bb[i] = (const float*)d_in[4 + 3 * i];
        }
    } else {                                // signature order
        for (int i = 0; i < 7; i++) {
            w[i]  = (const float*)d_in[2 + i];
            gg[i] = (const float*)d_in[9 + i];
            bb[i] = (const float*)d_in[16 + i];
        }
    }
    const float* clf_w = (const float*)d_in[23];
    const float* clf_b = (const float*)d_in[24];

    static int smem_set = 0;
    if (!smem_set) {
        cudaFuncSetAttribute(gemm_mma, cudaFuncAttributeMaxDynamicSharedMemorySize, SMEM_GEMM);
        smem_set = 1;
    }

    const int CIN[7]  = {3, 96, 96, 96, 192, 192, 192};
    const int FOUT[7] = {96, 96, 96, 192, 192, 192, 96};

    for (int l = 0; l < 7; l++) {
        const int C = CIN[l], F = FOUT[l], CK = C * KORD;

        // splits weights; also finalizes prev layer's BN and zeroes accumulators
        wsplit_bn<<<(F * CKP + 255) / 256, 256>>>(
            w[l], F, CK,
            l ? gg[l - 1] : nullptr, l ? bb[l - 1] : nullptr,
            l ? FOUT[l - 1] : 0, l ? 1 : 0);

        cheb_expand<<<dim3(C, GB), GV>>>(x, C, l == 0 ? 1 : 0);

        dim3 grid(F / 96, NN / 128);
        gemm_mma<<<grid, 256, SMEM_GEMM>>>(F, CK);
    }

    bn_final<<<1, 192>>>(gg[6], bb[6], 96);
    classifier<<<32, 256>>>(clf_w, clf_b, (float*)d_out);
}